// round 4
// baseline (speedup 1.0000x reference)
#include <cuda_runtime.h>
#include <math.h>

#define D      1024
#define H      4096
#define E      8
#define MAXT   4096
#define MAXP   (2*MAXT)

// ---------------- device scratch (static, allocation-free) ----------------
__device__ float g_h[(long long)MAXP * H];   // gelu(x@w1+b1) per pair  (134 MB)
__device__ float g_y[(long long)MAXP * D];   // h@w2 per pair           (33.5 MB)
__device__ int   g_tok[MAXP];                // slot -> token
__device__ float g_w[MAXP];                  // slot -> combine weight (unused in gemm; kept for debug)
__device__ int   g_topi[MAXP];               // token,k -> expert
__device__ float g_topw[MAXP];               // token,k -> normalized weight
__device__ int   g_pair_slot[MAXP];          // token,k -> slot
__device__ int   g_count[E];
__device__ int   g_offs[E];
__device__ int   g_cursor[E];
__device__ float g_probsum[E];

// ---------------- tiny setup kernels ----------------
__global__ void k_zero() {
    int i = threadIdx.x;
    if (i < E) { g_count[i] = 0; g_cursor[i] = 0; g_probsum[i] = 0.f; }
}

// one warp per token: logits (fp64 accum), softmax, top-2, counts, prob sums
__global__ void k_router(const float* __restrict__ x,
                         const float* __restrict__ rw,
                         const float* __restrict__ rb, int T) {
    __shared__ float sprob[E];
    int warp = threadIdx.x >> 5, lane = threadIdx.x & 31;
    int t = blockIdx.x * 8 + warp;
    if (threadIdx.x < E) sprob[threadIdx.x] = 0.f;
    __syncthreads();

    if (t < T) {
        double acc[E];
        #pragma unroll
        for (int e = 0; e < E; e++) acc[e] = 0.0;
        const float* xr = x + (size_t)t * D;
        for (int j = lane; j < D; j += 32) {
            float xv = xr[j];
            const float4* w4 = reinterpret_cast<const float4*>(rw + (size_t)j * E);
            float4 wa = w4[0], wb = w4[1];
            double xd = (double)xv;
            acc[0] += xd * (double)wa.x;  acc[1] += xd * (double)wa.y;
            acc[2] += xd * (double)wa.z;  acc[3] += xd * (double)wa.w;
            acc[4] += xd * (double)wb.x;  acc[5] += xd * (double)wb.y;
            acc[6] += xd * (double)wb.z;  acc[7] += xd * (double)wb.w;
        }
        #pragma unroll
        for (int e = 0; e < E; e++) {
            #pragma unroll
            for (int o = 16; o > 0; o >>= 1)
                acc[e] += __shfl_xor_sync(0xffffffffu, acc[e], o);
        }
        if (lane == 0) {
            float lg[E], mx = -1e30f;
            #pragma unroll
            for (int e = 0; e < E; e++) { lg[e] = (float)acc[e] + rb[e]; mx = fmaxf(mx, lg[e]); }
            float p[E], s = 0.f;
            #pragma unroll
            for (int e = 0; e < E; e++) { p[e] = expf(lg[e] - mx); s += p[e]; }
            float inv = 1.f / s;
            #pragma unroll
            for (int e = 0; e < E; e++) { p[e] *= inv; atomicAdd(&sprob[e], p[e]); }
            // top-2 (ties -> lower index, matches lax.top_k)
            int i0 = 0;
            #pragma unroll
            for (int e = 1; e < E; e++) if (p[e] > p[i0]) i0 = e;
            int i1 = -1;
            #pragma unroll
            for (int e = 0; e < E; e++) {
                if (e == i0) continue;
                if (i1 < 0 || p[e] > p[i1]) i1 = e;
            }
            float sw = p[i0] + p[i1];
            g_topi[2*t]   = i0;  g_topw[2*t]   = p[i0] / sw;
            g_topi[2*t+1] = i1;  g_topw[2*t+1] = p[i1] / sw;
            atomicAdd(&g_count[i0], 1);
            atomicAdd(&g_count[i1], 1);
        }
    }
    __syncthreads();
    if (threadIdx.x < E) atomicAdd(&g_probsum[threadIdx.x], sprob[threadIdx.x]);
}

// 1 thread: exclusive scan of counts + aux loss (var ddof=1 of mean probs)
__global__ void k_offs_aux(float* aux, int T) {
    int o = 0;
    for (int e = 0; e < E; e++) { g_offs[e] = o; g_cursor[e] = o; o += g_count[e]; }
    if (aux) {
        float m[E], mean = 0.f;
        for (int e = 0; e < E; e++) { m[e] = g_probsum[e] / (float)T; mean += m[e]; }
        mean /= (float)E;
        float v = 0.f;
        for (int e = 0; e < E; e++) { float d = m[e] - mean; v += d * d; }
        *aux = v / (float)(E - 1);
    }
}

__global__ void k_scatter(int T) {
    int t = blockIdx.x * blockDim.x + threadIdx.x;
    if (t >= T) return;
    #pragma unroll
    for (int k = 0; k < 2; k++) {
        int e = g_topi[2*t + k];
        int slot = atomicAdd(&g_cursor[e], 1);
        g_tok[slot] = t;
        g_w[slot]   = g_topw[2*t + k];
        g_pair_slot[2*t + k] = slot;
    }
}

// ---------------- grouped SGEMM 1: h = gelu(X_e @ w1[e] + b1[e]) ----------------
// 128x128 tile, BK=8, 256 threads, 8x8 micro-tile (strided 4+4 fragments)
__global__ __launch_bounds__(256)
void k_gemm1(const float* __restrict__ x, const float* __restrict__ w1,
             const float* __restrict__ b1) {
    int e   = blockIdx.z;
    int cnt = g_count[e];
    int m0  = blockIdx.y * 128;
    if (m0 >= cnt) return;
    int n0   = blockIdx.x * 128;
    int base = g_offs[e];
    const float* B = w1 + (size_t)e * D * H;

    __shared__ float As[8][132];
    __shared__ float Bs[8][132];

    int tid  = threadIdx.x;
    int arow = tid >> 1;                 // 0..127
    int acol = (tid & 1) * 4;            // 0 / 4
    int am   = m0 + arow;
    const float* Arow = (am < cnt) ? (x + (size_t)g_tok[base + am] * D) : nullptr;
    int brow = tid >> 5;                 // 0..7
    int bcol = (tid & 31) * 4;
    int tx = tid & 15, ty = tid >> 4;

    float c[8][8];
    #pragma unroll
    for (int i = 0; i < 8; i++)
        #pragma unroll
        for (int j = 0; j < 8; j++) c[i][j] = 0.f;

    for (int kt = 0; kt < D; kt += 8) {
        float4 av = Arow ? *(const float4*)(Arow + kt + acol) : make_float4(0,0,0,0);
        float4 bv = *(const float4*)(B + (size_t)(kt + brow) * H + n0 + bcol);
        __syncthreads();
        As[acol+0][arow] = av.x;  As[acol+1][arow] = av.y;
        As[acol+2][arow] = av.z;  As[acol+3][arow] = av.w;
        *(float4*)&Bs[brow][bcol] = bv;
        __syncthreads();
        #pragma unroll
        for (int k = 0; k < 8; k++) {
            float a[8], b[8];
            *(float4*)&a[0] = *(const float4*)&As[k][ty*4];
            *(float4*)&a[4] = *(const float4*)&As[k][64 + ty*4];
            *(float4*)&b[0] = *(const float4*)&Bs[k][tx*4];
            *(float4*)&b[4] = *(const float4*)&Bs[k][64 + tx*4];
            #pragma unroll
            for (int i = 0; i < 8; i++)
                #pragma unroll
                for (int j = 0; j < 8; j++) c[i][j] = fmaf(a[i], b[j], c[i][j]);
        }
    }

    float bias[8];
    #pragma unroll
    for (int jh = 0; jh < 2; jh++)
        #pragma unroll
        for (int j = 0; j < 4; j++)
            bias[jh*4 + j] = b1[(size_t)e * H + n0 + jh*64 + tx*4 + j];

    #pragma unroll
    for (int ih = 0; ih < 2; ih++) {
        #pragma unroll
        for (int i = 0; i < 4; i++) {
            int m = m0 + ih*64 + ty*4 + i;
            if (m >= cnt) continue;
            float* hp = g_h + (size_t)(base + m) * H + n0;
            #pragma unroll
            for (int jh = 0; jh < 2; jh++) {
                float4 r;
                float v;
                v = c[ih*4+i][jh*4+0] + bias[jh*4+0]; r.x = 0.5f*v*(1.f+erff(v*0.70710678118654752f));
                v = c[ih*4+i][jh*4+1] + bias[jh*4+1]; r.y = 0.5f*v*(1.f+erff(v*0.70710678118654752f));
                v = c[ih*4+i][jh*4+2] + bias[jh*4+2]; r.z = 0.5f*v*(1.f+erff(v*0.70710678118654752f));
                v = c[ih*4+i][jh*4+3] + bias[jh*4+3]; r.w = 0.5f*v*(1.f+erff(v*0.70710678118654752f));
                *(float4*)(hp + jh*64 + tx*4) = r;
            }
        }
    }
}

// ---------------- grouped SGEMM 2: y = h_e @ w2[e] ----------------
__global__ __launch_bounds__(256)
void k_gemm2(const float* __restrict__ w2) {
    int e   = blockIdx.z;
    int cnt = g_count[e];
    int m0  = blockIdx.y * 128;
    if (m0 >= cnt) return;
    int n0   = blockIdx.x * 128;
    int base = g_offs[e];
    const float* B = w2 + (size_t)e * H * D;

    __shared__ float As[8][132];
    __shared__ float Bs[8][132];

    int tid  = threadIdx.x;
    int arow = tid >> 1;
    int acol = (tid & 1) * 4;
    int am   = m0 + arow;
    const float* Arow = (am < cnt) ? (g_h + (size_t)(base + am) * H) : nullptr;
    int brow = tid >> 5;
    int bcol = (tid & 31) * 4;
    int tx = tid & 15, ty = tid >> 4;

    float c[8][8];
    #pragma unroll
    for (int i = 0; i < 8; i++)
        #pragma unroll
        for (int j = 0; j < 8; j++) c[i][j] = 0.f;

    for (int kt = 0; kt < H; kt += 8) {
        float4 av = Arow ? *(const float4*)(Arow + kt + acol) : make_float4(0,0,0,0);
        float4 bv = *(const float4*)(B + (size_t)(kt + brow) * D + n0 + bcol);
        __syncthreads();
        As[acol+0][arow] = av.x;  As[acol+1][arow] = av.y;
        As[acol+2][arow] = av.z;  As[acol+3][arow] = av.w;
        *(float4*)&Bs[brow][bcol] = bv;
        __syncthreads();
        #pragma unroll
        for (int k = 0; k < 8; k++) {
            float a[8], b[8];
            *(float4*)&a[0] = *(const float4*)&As[k][ty*4];
            *(float4*)&a[4] = *(const float4*)&As[k][64 + ty*4];
            *(float4*)&b[0] = *(const float4*)&Bs[k][tx*4];
            *(float4*)&b[4] = *(const float4*)&Bs[k][64 + tx*4];
            #pragma unroll
            for (int i = 0; i < 8; i++)
                #pragma unroll
                for (int j = 0; j < 8; j++) c[i][j] = fmaf(a[i], b[j], c[i][j]);
        }
    }

    #pragma unroll
    for (int ih = 0; ih < 2; ih++) {
        #pragma unroll
        for (int i = 0; i < 4; i++) {
            int m = m0 + ih*64 + ty*4 + i;
            if (m >= cnt) continue;
            float* yp = g_y + (size_t)(base + m) * D + n0;
            #pragma unroll
            for (int jh = 0; jh < 2; jh++) {
                float4 r;
                r.x = c[ih*4+i][jh*4+0];
                r.y = c[ih*4+i][jh*4+1];
                r.z = c[ih*4+i][jh*4+2];
                r.w = c[ih*4+i][jh*4+3];
                *(float4*)(yp + jh*64 + tx*4) = r;
            }
        }
    }
}

// ---------------- weighted combine (deterministic, no atomics) ----------------
__global__ void k_combine(const float* __restrict__ b2, float* __restrict__ out, int T) {
    int t = blockIdx.x;
    if (t >= T) return;
    int   e0 = g_topi[2*t],      e1 = g_topi[2*t+1];
    float w0 = g_topw[2*t],      w1 = g_topw[2*t+1];
    int   s0 = g_pair_slot[2*t], s1 = g_pair_slot[2*t+1];
    const float4* y0 = (const float4*)(g_y + (size_t)s0 * D);
    const float4* y1 = (const float4*)(g_y + (size_t)s1 * D);
    const float4* c0 = (const float4*)(b2 + (size_t)e0 * D);
    const float4* c1 = (const float4*)(b2 + (size_t)e1 * D);
    float4* o = (float4*)(out + (size_t)t * D);
    for (int j = threadIdx.x; j < D/4; j += blockDim.x) {
        float4 a = y0[j], b = y1[j], ba = c0[j], bb = c1[j];
        float4 r;
        r.x = w0*(a.x + ba.x) + w1*(b.x + bb.x);
        r.y = w0*(a.y + ba.y) + w1*(b.y + bb.y);
        r.z = w0*(a.z + ba.z) + w1*(b.z + bb.z);
        r.w = w0*(a.w + ba.w) + w1*(b.w + bb.w);
        o[j] = r;
    }
}

// ---------------- launch ----------------
extern "C" void kernel_launch(void* const* d_in, const int* in_sizes, int n_in,
                              void* d_out, int out_size) {
    const float* x  = (const float*)d_in[0];
    const float* rw = (const float*)d_in[1];
    const float* rb = (const float*)d_in[2];
    const float* w1 = (const float*)d_in[3];
    const float* b1 = (const float*)d_in[4];
    const float* w2 = (const float*)d_in[5];
    const float* b2 = (const float*)d_in[6];
    float* out = (float*)d_out;

    int T = in_sizes[0] / D;                 // 4096
    float* auxp = (out_size > T * D) ? (out + (size_t)T * D) : nullptr;

    k_zero<<<1, 32>>>();
    k_router<<<(T + 7) / 8, 256>>>(x, rw, rb, T);
    k_offs_aux<<<1, 1>>>(auxp, T);
    k_scatter<<<(T + 255) / 256, 256>>>(T);

    dim3 g1(H / 128, (T + 127) / 128, E);
    k_gemm1<<<g1, 256>>>(x, w1, b1);

    dim3 g2(D / 128, (T + 127) / 128, E);
    k_gemm2<<<g2, 256>>>(w2);

    k_combine<<<T, 256>>>(b2, out, T);
}

// round 8
// speedup vs baseline: 2.3500x; 2.3500x over previous
#include <cuda_runtime.h>
#include <cuda_bf16.h>
#include <math.h>
#include <stdint.h>

#define D      1024
#define H      4096
#define E      8
#define MAXT   4096
#define MAXP   (2*MAXT)
#define MAXPP  (MAXP + 128)          // padding so partial M-tiles never read OOB

#define TILEB  16384                 // 128 rows x 128 bytes (bf16 x64)
#define STAGEB (4*TILEB)             // Ah, Al, Bh, Bl
#define NSTAGE 3
#define SMEM_DYN (1024 + NSTAGE*STAGEB)

// ---------------- device scratch (static, allocation-free) ----------------
__device__ __align__(256) __nv_bfloat16 g_xh[(size_t)MAXPP*D];
__device__ __align__(256) __nv_bfloat16 g_xl[(size_t)MAXPP*D];
__device__ __align__(256) __nv_bfloat16 g_hh[(size_t)MAXPP*H];
__device__ __align__(256) __nv_bfloat16 g_hl[(size_t)MAXPP*H];
__device__ __align__(256) __nv_bfloat16 g_w1h[(size_t)E*D*H];  // [e][n(H)][k(D)]
__device__ __align__(256) __nv_bfloat16 g_w1l[(size_t)E*D*H];
__device__ __align__(256) __nv_bfloat16 g_w2h[(size_t)E*D*H];  // [e][n(D)][k(H)]
__device__ __align__(256) __nv_bfloat16 g_w2l[(size_t)E*D*H];
__device__ __align__(256) float g_y[(size_t)MAXP*D];
__device__ int   g_tok[MAXP];
__device__ int   g_topi[MAXP];
__device__ float g_topw[MAXP];
__device__ int   g_pair_slot[MAXP];
__device__ int   g_count[E];
__device__ int   g_offs[E];
__device__ int   g_cursor[E];
__device__ float g_probsum[E];

// ---------------- PTX helpers (all portable sm_80+ — NO tcgen05) ----------------
__device__ __forceinline__ uint32_t smem_u32(const void* p) {
    uint32_t a;
    asm("{ .reg .u64 t; cvta.to.shared.u64 t, %1; cvt.u32.u64 %0, t; }" : "=r"(a) : "l"(p));
    return a;
}
__device__ __forceinline__ void cpa16(uint32_t s, const void* g) {
    asm volatile("cp.async.cg.shared.global [%0], [%1], 16;" :: "r"(s), "l"(g));
}
#define CP_COMMIT() asm volatile("cp.async.commit_group;" ::: "memory")
#define CP_WAIT1()  asm volatile("cp.async.wait_group 1;" ::: "memory")

__device__ __forceinline__ void ldsm4(uint32_t* r, uint32_t addr) {
    asm volatile("ldmatrix.sync.aligned.m8n8.x4.shared.b16 {%0,%1,%2,%3}, [%4];"
        : "=r"(r[0]), "=r"(r[1]), "=r"(r[2]), "=r"(r[3]) : "r"(addr));
}
__device__ __forceinline__ void mma16816(float* c, const uint32_t* a, const uint32_t* b) {
    asm volatile("mma.sync.aligned.m16n8k16.row.col.f32.bf16.bf16.f32 "
        "{%0,%1,%2,%3}, {%4,%5,%6,%7}, {%8,%9}, {%0,%1,%2,%3};"
        : "+f"(c[0]), "+f"(c[1]), "+f"(c[2]), "+f"(c[3])
        : "r"(a[0]), "r"(a[1]), "r"(a[2]), "r"(a[3]), "r"(b[0]), "r"(b[1]));
}
__device__ __forceinline__ void bsplit(float v, __nv_bfloat16& hi, __nv_bfloat16& lo) {
    hi = __float2bfloat16(v);
    lo = __float2bfloat16(v - __bfloat162float(hi));
}

// ---------------- tiny setup kernels ----------------
__global__ void k_zero() {
    int i = threadIdx.x;
    if (i < E) { g_count[i] = 0; g_cursor[i] = 0; g_probsum[i] = 0.f; }
}

// one warp per token: logits (fp64 accum), softmax, top-2
__global__ void k_router(const float* __restrict__ x,
                         const float* __restrict__ rw,
                         const float* __restrict__ rb, int T) {
    __shared__ float sprob[E];
    int warp = threadIdx.x >> 5, lane = threadIdx.x & 31;
    int t = blockIdx.x * 8 + warp;
    if (threadIdx.x < E) sprob[threadIdx.x] = 0.f;
    __syncthreads();

    if (t < T) {
        double acc[E];
        #pragma unroll
        for (int e = 0; e < E; e++) acc[e] = 0.0;
        const float* xr = x + (size_t)t * D;
        for (int j = lane; j < D; j += 32) {
            float xv = xr[j];
            const float4* w4 = reinterpret_cast<const float4*>(rw + (size_t)j * E);
            float4 wa = w4[0], wb = w4[1];
            double xd = (double)xv;
            acc[0] += xd * (double)wa.x;  acc[1] += xd * (double)wa.y;
            acc[2] += xd * (double)wa.z;  acc[3] += xd * (double)wa.w;
            acc[4] += xd * (double)wb.x;  acc[5] += xd * (double)wb.y;
            acc[6] += xd * (double)wb.z;  acc[7] += xd * (double)wb.w;
        }
        #pragma unroll
        for (int e = 0; e < E; e++) {
            #pragma unroll
            for (int o = 16; o > 0; o >>= 1)
                acc[e] += __shfl_xor_sync(0xffffffffu, acc[e], o);
        }
        if (lane == 0) {
            float lg[E], mx = -1e30f;
            #pragma unroll
            for (int e = 0; e < E; e++) { lg[e] = (float)acc[e] + rb[e]; mx = fmaxf(mx, lg[e]); }
            float p[E], s = 0.f;
            #pragma unroll
            for (int e = 0; e < E; e++) { p[e] = expf(lg[e] - mx); s += p[e]; }
            float inv = 1.f / s;
            #pragma unroll
            for (int e = 0; e < E; e++) { p[e] *= inv; atomicAdd(&sprob[e], p[e]); }
            int i0 = 0;
            #pragma unroll
            for (int e = 1; e < E; e++) if (p[e] > p[i0]) i0 = e;
            int i1 = -1;
            #pragma unroll
            for (int e = 0; e < E; e++) {
                if (e == i0) continue;
                if (i1 < 0 || p[e] > p[i1]) i1 = e;
            }
            float sw = p[i0] + p[i1];
            g_topi[2*t]   = i0;  g_topw[2*t]   = p[i0] / sw;
            g_topi[2*t+1] = i1;  g_topw[2*t+1] = p[i1] / sw;
            atomicAdd(&g_count[i0], 1);
            atomicAdd(&g_count[i1], 1);
        }
    }
    __syncthreads();
    if (threadIdx.x < E) atomicAdd(&g_probsum[threadIdx.x], sprob[threadIdx.x]);
}

__global__ void k_offs_aux(float* aux, int T) {
    int o = 0;
    for (int e = 0; e < E; e++) { g_offs[e] = o; g_cursor[e] = o; o += g_count[e]; }
    if (aux) {
        float m[E], mean = 0.f;
        for (int e = 0; e < E; e++) { m[e] = g_probsum[e] / (float)T; mean += m[e]; }
        mean /= (float)E;
        float v = 0.f;
        for (int e = 0; e < E; e++) { float d = m[e] - mean; v += d * d; }
        *aux = v / (float)(E - 1);
    }
}

__global__ void k_scatter(int T) {
    int t = blockIdx.x * blockDim.x + threadIdx.x;
    if (t >= T) return;
    #pragma unroll
    for (int k = 0; k < 2; k++) {
        int e = g_topi[2*t + k];
        int slot = atomicAdd(&g_cursor[e], 1);
        g_tok[slot] = t;
        g_pair_slot[2*t + k] = slot;
    }
}

// gather token rows into slot order, split to bf16 hi/lo. grid = 2T, block = 256
__global__ void k_gather(const float* __restrict__ x) {
    int slot = blockIdx.x;
    int tok  = g_tok[slot];
    const float4* xr = (const float4*)(x + (size_t)tok * D);
    int j = threadIdx.x;               // D/4 = 256
    float4 v = xr[j];
    __nv_bfloat16 h0,l0,h1,l1,h2,l2,h3,l3;
    bsplit(v.x,h0,l0); bsplit(v.y,h1,l1); bsplit(v.z,h2,l2); bsplit(v.w,h3,l3);
    __nv_bfloat162* ph = (__nv_bfloat162*)(g_xh + (size_t)slot*D + j*4);
    __nv_bfloat162* pl = (__nv_bfloat162*)(g_xl + (size_t)slot*D + j*4);
    __nv_bfloat162 a; a.x=h0; a.y=h1; ph[0]=a;
    __nv_bfloat162 b; b.x=h2; b.y=h3; ph[1]=b;
    __nv_bfloat162 c; c.x=l0; c.y=l1; pl[0]=c;
    __nv_bfloat162 d; d.x=l2; d.y=l3; pl[1]=d;
}

// transpose [R x C] -> [C x R] per expert + bf16 split. which: 0 -> w1, 1 -> w2
__global__ void k_wsplit(const float* __restrict__ W, int R, int C, int which) {
    __shared__ float t[32][33];
    __nv_bfloat16* oh = which ? g_w2h : g_w1h;
    __nv_bfloat16* ol = which ? g_w2l : g_w1l;
    int e = blockIdx.z;
    const float* src = W + (size_t)e * R * C;
    int c0 = blockIdx.x * 32, r0 = blockIdx.y * 32;
    int tx = threadIdx.x, ty = threadIdx.y;          // 32 x 8
    #pragma unroll
    for (int i = 0; i < 32; i += 8)
        t[ty + i][tx] = src[(size_t)(r0 + ty + i) * C + c0 + tx];
    __syncthreads();
    size_t ob = (size_t)e * R * C;
    #pragma unroll
    for (int i = 0; i < 32; i += 8) {
        float v = t[tx][ty + i];
        __nv_bfloat16 h, l; bsplit(v, h, l);
        size_t idx = ob + (size_t)(c0 + ty + i) * R + r0 + tx;
        oh[idx] = h; ol[idx] = l;
    }
}

// ---------------- HMMA grouped GEMM core ----------------
// load one K-chunk (64 elts) for 4 tiles (Ah, Al, Bh, Bl) into a stage.
// SW128 swizzle: x ^ ((x>>3)&0x70). 16 cp.async per thread.
__device__ __forceinline__ void stage_load(uint32_t st,
    const __nv_bfloat16* __restrict__ Ah, const __nv_bfloat16* __restrict__ Al,
    const __nv_bfloat16* __restrict__ Bh, const __nv_bfloat16* __restrict__ Bl,
    int ldk, int koff, int tid)
{
    #pragma unroll
    for (int i = 0; i < 4; i++) {
        int c   = tid + i * 256;            // 0..1023
        int row = c >> 3, ch = c & 7;
        uint32_t x  = (uint32_t)((row << 7) + (ch << 4));
        uint32_t sw = x ^ ((x >> 3) & 0x70);
        size_t g = (size_t)row * ldk + koff + ch * 8;
        cpa16(st + 0*TILEB + sw, Ah + g);
        cpa16(st + 1*TILEB + sw, Al + g);
        cpa16(st + 2*TILEB + sw, Bh + g);
        cpa16(st + 3*TILEB + sw, Bl + g);
    }
}

// compute one stage: 4 k16-steps, warp tile 64x32, 3-pass bf16 split
__device__ __forceinline__ void mma_stage(float (*acc)[4][4], uint32_t st,
                                          int wm0, int wn0, int lane)
{
    uint32_t sAh = st, sAl = st + TILEB, sBh = st + 2*TILEB, sBl = st + 3*TILEB;
    #pragma unroll
    for (int kk = 0; kk < 4; kk++) {
        uint32_t ah[4][4], al[4][4], bh[2][4], bl[2][4];
        int ab = kk*32 + ((lane >> 4) << 4);
        #pragma unroll
        for (int mf = 0; mf < 4; mf++) {
            uint32_t x  = (uint32_t)((wm0 + mf*16 + (lane & 15)) << 7) + ab;
            uint32_t sw = x ^ ((x >> 3) & 0x70);
            ldsm4(ah[mf], sAh + sw);
            ldsm4(al[mf], sAl + sw);
        }
        int bb = kk*32 + ((lane & 8) << 1);
        int br = (lane & 7) + ((lane & 16) >> 1);
        #pragma unroll
        for (int nf2 = 0; nf2 < 2; nf2++) {
            uint32_t x  = (uint32_t)((wn0 + nf2*16 + br) << 7) + bb;
            uint32_t sw = x ^ ((x >> 3) & 0x70);
            ldsm4(bh[nf2], sBh + sw);
            ldsm4(bl[nf2], sBl + sw);
        }
        #pragma unroll
        for (int mf = 0; mf < 4; mf++) {
            #pragma unroll
            for (int nf = 0; nf < 4; nf++) {
                const uint32_t* pbh = &bh[nf >> 1][(nf & 1) * 2];
                const uint32_t* pbl = &bl[nf >> 1][(nf & 1) * 2];
                mma16816(acc[mf][nf], ah[mf], pbh);   // hi*hi
                mma16816(acc[mf][nf], al[mf], pbh);   // lo*hi
                mma16816(acc[mf][nf], ah[mf], pbl);   // hi*lo
            }
        }
    }
}

// mainloop: 3-stage cp.async pipeline; returns with acc filled
__device__ __forceinline__ void gemm_main(float (*acc)[4][4], uint32_t ub,
    const __nv_bfloat16* Ah, const __nv_bfloat16* Al,
    const __nv_bfloat16* Bh, const __nv_bfloat16* Bl,
    int ldk, int nk, int tid, int wm0, int wn0, int lane)
{
    stage_load(ub + 0*STAGEB, Ah, Al, Bh, Bl, ldk, 0,  tid); CP_COMMIT();
    stage_load(ub + 1*STAGEB, Ah, Al, Bh, Bl, ldk, 64, tid); CP_COMMIT();
    for (int kt = 0; kt < nk; kt++) {
        CP_WAIT1();
        __syncthreads();
        if (kt + 2 < nk) {
            stage_load(ub + ((kt + 2) % NSTAGE) * STAGEB, Ah, Al, Bh, Bl,
                       ldk, (kt + 2) * 64, tid);
            CP_COMMIT();
        }
        mma_stage(acc, ub + (kt % NSTAGE) * STAGEB, wm0, wn0, lane);
    }
}

// GEMM1: h = gelu(Xg @ w1t^T + b1) -> bf16 hi/lo
__global__ __launch_bounds__(256, 1)
void k_gemm1_mma(const float* __restrict__ b1) {
    int e   = blockIdx.z;
    int cnt = g_count[e];
    int m0  = blockIdx.y * 128;
    if (m0 >= cnt) return;
    int n0   = blockIdx.x * 128;
    int base = g_offs[e];

    extern __shared__ char smem[];
    uint32_t ub = (smem_u32(smem) + 1023u) & ~1023u;
    int tid = threadIdx.x, lane = tid & 31, wid = tid >> 5;
    int wm0 = (wid >> 2) * 64, wn0 = (wid & 3) * 32;

    const __nv_bfloat16* Ah = g_xh  + (size_t)(base + m0) * D;
    const __nv_bfloat16* Al = g_xl  + (size_t)(base + m0) * D;
    const __nv_bfloat16* Bh = g_w1h + (size_t)e * H * D + (size_t)n0 * D;
    const __nv_bfloat16* Bl = g_w1l + (size_t)e * H * D + (size_t)n0 * D;

    float acc[4][4][4] = {};
    gemm_main(acc, ub, Ah, Al, Bh, Bl, D, D / 64, tid, wm0, wn0, lane);

    // epilogue: bias + exact gelu + bf16 split store
    int cb = (lane & 3) * 2;       // n within frag
    int mr = lane >> 2;            // m within frag
    const float* bp = b1 + (size_t)e * H + n0 + wn0;
    #pragma unroll
    for (int nf = 0; nf < 4; nf++) {
        float bv0 = bp[nf*8 + cb], bv1 = bp[nf*8 + cb + 1];
        #pragma unroll
        for (int mf = 0; mf < 4; mf++) {
            #pragma unroll
            for (int rr = 0; rr < 2; rr++) {
                int m = m0 + wm0 + mf*16 + mr + rr*8;
                if (m >= cnt) continue;
                float v0 = acc[mf][nf][rr*2]     + bv0;
                float v1 = acc[mf][nf][rr*2 + 1] + bv1;
                float e0 = 0.5f * v0 * (1.f + erff(v0 * 0.70710678118654752f));
                float e1 = 0.5f * v1 * (1.f + erff(v1 * 0.70710678118654752f));
                __nv_bfloat16 h0,l0,h1,l1; bsplit(e0,h0,l0); bsplit(e1,h1,l1);
                size_t o = (size_t)(base + m) * H + n0 + wn0 + nf*8 + cb;
                __nv_bfloat162 ph; ph.x=h0; ph.y=h1;
                __nv_bfloat162 pl; pl.x=l0; pl.y=l1;
                *reinterpret_cast<__nv_bfloat162*>(g_hh + o) = ph;
                *reinterpret_cast<__nv_bfloat162*>(g_hl + o) = pl;
            }
        }
    }
}

// GEMM2: y = h @ w2t^T (fp32 out)
__global__ __launch_bounds__(256, 1)
void k_gemm2_mma() {
    int e   = blockIdx.z;
    int cnt = g_count[e];
    int m0  = blockIdx.y * 128;
    if (m0 >= cnt) return;
    int n0   = blockIdx.x * 128;
    int base = g_offs[e];

    extern __shared__ char smem[];
    uint32_t ub = (smem_u32(smem) + 1023u) & ~1023u;
    int tid = threadIdx.x, lane = tid & 31, wid = tid >> 5;
    int wm0 = (wid >> 2) * 64, wn0 = (wid & 3) * 32;

    const __nv_bfloat16* Ah = g_hh  + (size_t)(base + m0) * H;
    const __nv_bfloat16* Al = g_hl  + (size_t)(base + m0) * H;
    const __nv_bfloat16* Bh = g_w2h + (size_t)e * D * H + (size_t)n0 * H;
    const __nv_bfloat16* Bl = g_w2l + (size_t)e * D * H + (size_t)n0 * H;

    float acc[4][4][4] = {};
    gemm_main(acc, ub, Ah, Al, Bh, Bl, H, H / 64, tid, wm0, wn0, lane);

    int cb = (lane & 3) * 2;
    int mr = lane >> 2;
    #pragma unroll
    for (int nf = 0; nf < 4; nf++) {
        #pragma unroll
        for (int mf = 0; mf < 4; mf++) {
            #pragma unroll
            for (int rr = 0; rr < 2; rr++) {
                int m = m0 + wm0 + mf*16 + mr + rr*8;
                if (m >= cnt) continue;
                float2 v;
                v.x = acc[mf][nf][rr*2];
                v.y = acc[mf][nf][rr*2 + 1];
                *reinterpret_cast<float2*>(
                    g_y + (size_t)(base + m) * D + n0 + wn0 + nf*8 + cb) = v;
            }
        }
    }
}

// ---------------- weighted combine (deterministic) ----------------
__global__ void k_combine(const float* __restrict__ b2, float* __restrict__ out, int T) {
    int t = blockIdx.x;
    if (t >= T) return;
    int   e0 = g_topi[2*t],      e1 = g_topi[2*t+1];
    float w0 = g_topw[2*t],      w1 = g_topw[2*t+1];
    int   s0 = g_pair_slot[2*t], s1 = g_pair_slot[2*t+1];
    const float4* y0 = (const float4*)(g_y + (size_t)s0 * D);
    const float4* y1 = (const float4*)(g_y + (size_t)s1 * D);
    const float4* c0 = (const float4*)(b2 + (size_t)e0 * D);
    const float4* c1 = (const float4*)(b2 + (size_t)e1 * D);
    float4* o = (float4*)(out + (size_t)t * D);
    for (int j = threadIdx.x; j < D/4; j += blockDim.x) {
        float4 a = y0[j], b = y1[j], ba = c0[j], bb = c1[j];
        float4 r;
        r.x = w0*(a.x + ba.x) + w1*(b.x + bb.x);
        r.y = w0*(a.y + ba.y) + w1*(b.y + bb.y);
        r.z = w0*(a.z + ba.z) + w1*(b.z + bb.z);
        r.w = w0*(a.w + ba.w) + w1*(b.w + bb.w);
        o[j] = r;
    }
}

// ---------------- launch ----------------
extern "C" void kernel_launch(void* const* d_in, const int* in_sizes, int n_in,
                              void* d_out, int out_size) {
    const float* x  = (const float*)d_in[0];
    const float* rw = (const float*)d_in[1];
    const float* rb = (const float*)d_in[2];
    const float* w1 = (const float*)d_in[3];
    const float* b1 = (const float*)d_in[4];
    const float* w2 = (const float*)d_in[5];
    const float* b2 = (const float*)d_in[6];
    float* out = (float*)d_out;

    int T = in_sizes[0] / D;                 // 4096
    float* auxp = (out_size > T * D) ? (out + (size_t)T * D) : nullptr;

    cudaFuncSetAttribute(k_gemm1_mma, cudaFuncAttributeMaxDynamicSharedMemorySize, SMEM_DYN);
    cudaFuncSetAttribute(k_gemm2_mma, cudaFuncAttributeMaxDynamicSharedMemorySize, SMEM_DYN);

    k_zero<<<1, 32>>>();

    // weight transpose + bf16 split (independent of router)
    dim3 tb(32, 8);
    k_wsplit<<<dim3(H/32, D/32, E), tb>>>(w1, D, H, 0);
    k_wsplit<<<dim3(D/32, H/32, E), tb>>>(w2, H, D, 1);

    k_router<<<(T + 7) / 8, 256>>>(x, rw, rb, T);
    k_offs_aux<<<1, 1>>>(auxp, T);
    k_scatter<<<(T + 255) / 256, 256>>>(T);
    k_gather<<<2 * T, 256>>>(x);

    int mtiles = (2 * T + 127) / 128;        // upper bound on any expert's tiles
    k_gemm1_mma<<<dim3(H/128, mtiles, E), 256, SMEM_DYN>>>(b1);
    k_gemm2_mma<<<dim3(D/128, mtiles, E), 256, SMEM_DYN>>>();

    k_combine<<<T, 256>>>(b2, out, T);
}

// round 10
// speedup vs baseline: 3.7110x; 1.5792x over previous
#include <cuda_runtime.h>
#include <cuda_fp16.h>
#include <math.h>
#include <stdint.h>

#define D      1024
#define H      4096
#define E      8
#define MAXT   4096
#define MAXP   (2*MAXT)
#define MAXPP  (MAXP + 128)          // padding so partial M-tiles never read OOB

#define TILEB  16384                 // 128 rows x 128 bytes (fp16 x64)
#define STAGEB (3*TILEB)             // Ah, Al, Bh
#define NSTAGE 4
#define SMEM_DYN (1024 + NSTAGE*STAGEB)

// ---------------- device scratch (static, allocation-free) ----------------
__device__ __align__(256) __half g_xh[(size_t)MAXPP*D];
__device__ __align__(256) __half g_xl[(size_t)MAXPP*D];
__device__ __align__(256) __half g_hh[(size_t)MAXPP*H];
__device__ __align__(256) __half g_hl[(size_t)MAXPP*H];
__device__ __align__(256) __half g_w1h[(size_t)E*D*H];  // [e][n(H)][k(D)]
__device__ __align__(256) __half g_w2h[(size_t)E*D*H];  // [e][n(D)][k(H)]
__device__ __align__(256) float g_y[(size_t)MAXP*D];
__device__ int   g_tok[MAXP];
__device__ int   g_topi[MAXP];
__device__ float g_topw[MAXP];
__device__ int   g_pair_slot[MAXP];
__device__ int   g_count[E];
__device__ int   g_offs[E];
__device__ int   g_cursor[E];
__device__ float g_probsum[E];

// ---------------- PTX helpers (portable sm_80+) ----------------
__device__ __forceinline__ uint32_t smem_u32(const void* p) {
    uint32_t a;
    asm("{ .reg .u64 t; cvta.to.shared.u64 t, %1; cvt.u32.u64 %0, t; }" : "=r"(a) : "l"(p));
    return a;
}
__device__ __forceinline__ void cpa16(uint32_t s, const void* g) {
    asm volatile("cp.async.cg.shared.global [%0], [%1], 16;" :: "r"(s), "l"(g));
}
#define CP_COMMIT() asm volatile("cp.async.commit_group;" ::: "memory")
#define CP_WAIT2()  asm volatile("cp.async.wait_group 2;" ::: "memory")

__device__ __forceinline__ void ldsm4(uint32_t* r, uint32_t addr) {
    asm volatile("ldmatrix.sync.aligned.m8n8.x4.shared.b16 {%0,%1,%2,%3}, [%4];"
        : "=r"(r[0]), "=r"(r[1]), "=r"(r[2]), "=r"(r[3]) : "r"(addr));
}
__device__ __forceinline__ void mma16816(float* c, const uint32_t* a, const uint32_t* b) {
    asm volatile("mma.sync.aligned.m16n8k16.row.col.f32.f16.f16.f32 "
        "{%0,%1,%2,%3}, {%4,%5,%6,%7}, {%8,%9}, {%0,%1,%2,%3};"
        : "+f"(c[0]), "+f"(c[1]), "+f"(c[2]), "+f"(c[3])
        : "r"(a[0]), "r"(a[1]), "r"(a[2]), "r"(a[3]), "r"(b[0]), "r"(b[1]));
}
__device__ __forceinline__ void hsplit(float v, __half& hi, __half& lo) {
    hi = __float2half(v);
    lo = __float2half(v - __half2float(hi));
}

// ---------------- tiny setup kernels ----------------
__global__ void k_zero() {
    int i = threadIdx.x;
    if (i < E) { g_count[i] = 0; g_cursor[i] = 0; g_probsum[i] = 0.f; }
}

// one warp per token: logits via compensated fp32 (TwoProdFMA + Kahan), softmax, top-2
__global__ void k_router(const float* __restrict__ x,
                         const float* __restrict__ rw,
                         const float* __restrict__ rb, int T) {
    __shared__ float sprob[E];
    int warp = threadIdx.x >> 5, lane = threadIdx.x & 31;
    int t = blockIdx.x * 8 + warp;
    if (threadIdx.x < E) sprob[threadIdx.x] = 0.f;
    __syncthreads();

    if (t < T) {
        float s[E], c[E];                       // kahan: true = s - c
        #pragma unroll
        for (int e = 0; e < E; e++) { s[e] = 0.f; c[e] = 0.f; }
        const float* xr = x + (size_t)t * D;
        for (int j = lane; j < D; j += 32) {
            float xv = xr[j];
            const float4* w4 = reinterpret_cast<const float4*>(rw + (size_t)j * E);
            float4 wa = w4[0], wb = w4[1];
            float wv[E] = {wa.x, wa.y, wa.z, wa.w, wb.x, wb.y, wb.z, wb.w};
            #pragma unroll
            for (int e = 0; e < E; e++) {
                float ph = xv * wv[e];
                float pl = fmaf(xv, wv[e], -ph);    // exact product tail
                float yv = ph - c[e];
                float tt = s[e] + yv;
                c[e] = ((tt - s[e]) - yv) - pl;
                s[e] = tt;
            }
        }
        // compensated cross-lane reduction (TwoSum on s, fold error into c)
        #pragma unroll
        for (int e = 0; e < E; e++) {
            #pragma unroll
            for (int o = 16; o > 0; o >>= 1) {
                float s2 = __shfl_xor_sync(0xffffffffu, s[e], o);
                float c2 = __shfl_xor_sync(0xffffffffu, c[e], o);
                float tt = s[e] + s2;
                float bp = tt - s[e];
                float er = (s[e] - (tt - bp)) + (s2 - bp);
                s[e] = tt;
                c[e] = c[e] + c2 - er;
            }
        }
        if (lane == 0) {
            float lg[E], mx = -1e30f;
            #pragma unroll
            for (int e = 0; e < E; e++) { lg[e] = (s[e] - c[e]) + rb[e]; mx = fmaxf(mx, lg[e]); }
            float p[E], sm = 0.f;
            #pragma unroll
            for (int e = 0; e < E; e++) { p[e] = expf(lg[e] - mx); sm += p[e]; }
            float inv = 1.f / sm;
            #pragma unroll
            for (int e = 0; e < E; e++) { p[e] *= inv; atomicAdd(&sprob[e], p[e]); }
            int i0 = 0;
            #pragma unroll
            for (int e = 1; e < E; e++) if (p[e] > p[i0]) i0 = e;
            int i1 = -1;
            #pragma unroll
            for (int e = 0; e < E; e++) {
                if (e == i0) continue;
                if (i1 < 0 || p[e] > p[i1]) i1 = e;
            }
            float sw = p[i0] + p[i1];
            g_topi[2*t]   = i0;  g_topw[2*t]   = p[i0] / sw;
            g_topi[2*t+1] = i1;  g_topw[2*t+1] = p[i1] / sw;
            atomicAdd(&g_count[i0], 1);
            atomicAdd(&g_count[i1], 1);
        }
    }
    __syncthreads();
    if (threadIdx.x < E) atomicAdd(&g_probsum[threadIdx.x], sprob[threadIdx.x]);
}

__global__ void k_offs_aux(float* aux, int T) {
    int o = 0;
    for (int e = 0; e < E; e++) { g_offs[e] = o; g_cursor[e] = o; o += g_count[e]; }
    if (aux) {
        float m[E], mean = 0.f;
        for (int e = 0; e < E; e++) { m[e] = g_probsum[e] / (float)T; mean += m[e]; }
        mean /= (float)E;
        float v = 0.f;
        for (int e = 0; e < E; e++) { float d = m[e] - mean; v += d * d; }
        *aux = v / (float)(E - 1);
    }
}

__global__ void k_scatter(int T) {
    int t = blockIdx.x * blockDim.x + threadIdx.x;
    if (t >= T) return;
    #pragma unroll
    for (int k = 0; k < 2; k++) {
        int e = g_topi[2*t + k];
        int slot = atomicAdd(&g_cursor[e], 1);
        g_tok[slot] = t;
        g_pair_slot[2*t + k] = slot;
    }
}

// gather token rows into slot order, split to fp16 hi/lo. grid = 2T, block = 256
__global__ void k_gather(const float* __restrict__ x) {
    int slot = blockIdx.x;
    int tok  = g_tok[slot];
    const float4* xr = (const float4*)(x + (size_t)tok * D);
    int j = threadIdx.x;               // D/4 = 256
    float4 v = xr[j];
    __half h0,l0,h1,l1,h2,l2,h3,l3;
    hsplit(v.x,h0,l0); hsplit(v.y,h1,l1); hsplit(v.z,h2,l2); hsplit(v.w,h3,l3);
    __half2* ph = (__half2*)(g_xh + (size_t)slot*D + j*4);
    __half2* pl = (__half2*)(g_xl + (size_t)slot*D + j*4);
    ph[0] = __halves2half2(h0, h1);
    ph[1] = __halves2half2(h2, h3);
    pl[0] = __halves2half2(l0, l1);
    pl[1] = __halves2half2(l2, l3);
}

// transpose [R x C] -> [C x R] per expert + fp16 convert. which: 0 -> w1, 1 -> w2
__global__ void k_wsplit(const float* __restrict__ W, int R, int C, int which) {
    __shared__ float t[32][33];
    __half* oh = which ? g_w2h : g_w1h;
    int e = blockIdx.z;
    const float* src = W + (size_t)e * R * C;
    int c0 = blockIdx.x * 32, r0 = blockIdx.y * 32;
    int tx = threadIdx.x, ty = threadIdx.y;          // 32 x 8
    #pragma unroll
    for (int i = 0; i < 32; i += 8)
        t[ty + i][tx] = src[(size_t)(r0 + ty + i) * C + c0 + tx];
    __syncthreads();
    size_t ob = (size_t)e * R * C;
    #pragma unroll
    for (int i = 0; i < 32; i += 8) {
        float v = t[tx][ty + i];
        oh[ob + (size_t)(c0 + ty + i) * R + r0 + tx] = __float2half(v);
    }
}

// ---------------- HMMA grouped GEMM core (fp16 2-pass split) ----------------
// load one K-chunk (64 elts) for 3 tiles (Ah, Al, Bh) into a stage.
__device__ __forceinline__ void stage_load(uint32_t st,
    const __half* __restrict__ Ah, const __half* __restrict__ Al,
    const __half* __restrict__ Bh, int ldk, int koff, int tid)
{
    #pragma unroll
    for (int i = 0; i < 4; i++) {
        int c   = tid + i * 256;            // 0..1023
        int row = c >> 3, ch = c & 7;
        uint32_t x  = (uint32_t)((row << 7) + (ch << 4));
        uint32_t sw = x ^ ((x >> 3) & 0x70);
        size_t g = (size_t)row * ldk + koff + ch * 8;
        cpa16(st + 0*TILEB + sw, Ah + g);
        cpa16(st + 1*TILEB + sw, Al + g);
        cpa16(st + 2*TILEB + sw, Bh + g);
    }
}

// compute one stage: 4 k16-steps, warp tile 64x32, 2-pass fp16 split
__device__ __forceinline__ void mma_stage(float (*acc)[4][4], uint32_t st,
                                          int wm0, int wn0, int lane)
{
    uint32_t sAh = st, sAl = st + TILEB, sBh = st + 2*TILEB;
    #pragma unroll
    for (int kk = 0; kk < 4; kk++) {
        uint32_t ah[4][4], al[4][4], bh[2][4];
        int ab = kk*32 + ((lane >> 4) << 4);
        #pragma unroll
        for (int mf = 0; mf < 4; mf++) {
            uint32_t x  = (uint32_t)((wm0 + mf*16 + (lane & 15)) << 7) + ab;
            uint32_t sw = x ^ ((x >> 3) & 0x70);
            ldsm4(ah[mf], sAh + sw);
            ldsm4(al[mf], sAl + sw);
        }
        int bb = kk*32 + ((lane & 8) << 1);
        int br = (lane & 7) + ((lane & 16) >> 1);
        #pragma unroll
        for (int nf2 = 0; nf2 < 2; nf2++) {
            uint32_t x  = (uint32_t)((wn0 + nf2*16 + br) << 7) + bb;
            uint32_t sw = x ^ ((x >> 3) & 0x70);
            ldsm4(bh[nf2], sBh + sw);
        }
        #pragma unroll
        for (int mf = 0; mf < 4; mf++) {
            #pragma unroll
            for (int nf = 0; nf < 4; nf++) {
                const uint32_t* pbh = &bh[nf >> 1][(nf & 1) * 2];
                mma16816(acc[mf][nf], ah[mf], pbh);   // hi*B
                mma16816(acc[mf][nf], al[mf], pbh);   // lo*B
            }
        }
    }
}

// mainloop: 4-stage cp.async pipeline
__device__ __forceinline__ void gemm_main(float (*acc)[4][4], uint32_t ub,
    const __half* Ah, const __half* Al, const __half* Bh,
    int ldk, int nk, int tid, int wm0, int wn0, int lane)
{
    stage_load(ub + 0*STAGEB, Ah, Al, Bh, ldk, 0,   tid); CP_COMMIT();
    stage_load(ub + 1*STAGEB, Ah, Al, Bh, ldk, 64,  tid); CP_COMMIT();
    stage_load(ub + 2*STAGEB, Ah, Al, Bh, ldk, 128, tid); CP_COMMIT();
    for (int kt = 0; kt < nk; kt++) {
        CP_WAIT2();
        __syncthreads();
        if (kt + 3 < nk) {
            stage_load(ub + ((kt + 3) % NSTAGE) * STAGEB, Ah, Al, Bh,
                       ldk, (kt + 3) * 64, tid);
            CP_COMMIT();
        }
        mma_stage(acc, ub + (kt % NSTAGE) * STAGEB, wm0, wn0, lane);
    }
}

// GEMM1: h = gelu(Xg @ w1t^T + b1) -> fp16 hi/lo
__global__ __launch_bounds__(256, 1)
void k_gemm1_mma(const float* __restrict__ b1) {
    int e   = blockIdx.z;
    int cnt = g_count[e];
    int m0  = blockIdx.y * 128;
    if (m0 >= cnt) return;
    int n0   = blockIdx.x * 128;
    int base = g_offs[e];

    extern __shared__ char smem[];
    uint32_t ub = (smem_u32(smem) + 1023u) & ~1023u;
    int tid = threadIdx.x, lane = tid & 31, wid = tid >> 5;
    int wm0 = (wid >> 2) * 64, wn0 = (wid & 3) * 32;

    const __half* Ah = g_xh  + (size_t)(base + m0) * D;
    const __half* Al = g_xl  + (size_t)(base + m0) * D;
    const __half* Bh = g_w1h + (size_t)e * H * D + (size_t)n0 * D;

    float acc[4][4][4] = {};
    gemm_main(acc, ub, Ah, Al, Bh, D, D / 64, tid, wm0, wn0, lane);

    // epilogue: bias + exact gelu + fp16 split store
    int cb = (lane & 3) * 2;       // n within frag
    int mr = lane >> 2;            // m within frag
    const float* bp = b1 + (size_t)e * H + n0 + wn0;
    #pragma unroll
    for (int nf = 0; nf < 4; nf++) {
        float bv0 = bp[nf*8 + cb], bv1 = bp[nf*8 + cb + 1];
        #pragma unroll
        for (int mf = 0; mf < 4; mf++) {
            #pragma unroll
            for (int rr = 0; rr < 2; rr++) {
                int m = m0 + wm0 + mf*16 + mr + rr*8;
                if (m >= cnt) continue;
                float v0 = acc[mf][nf][rr*2]     + bv0;
                float v1 = acc[mf][nf][rr*2 + 1] + bv1;
                float e0 = 0.5f * v0 * (1.f + erff(v0 * 0.70710678118654752f));
                float e1 = 0.5f * v1 * (1.f + erff(v1 * 0.70710678118654752f));
                __half h0,l0,h1,l1; hsplit(e0,h0,l0); hsplit(e1,h1,l1);
                size_t o = (size_t)(base + m) * H + n0 + wn0 + nf*8 + cb;
                *reinterpret_cast<__half2*>(g_hh + o) = __halves2half2(h0, h1);
                *reinterpret_cast<__half2*>(g_hl + o) = __halves2half2(l0, l1);
            }
        }
    }
}

// GEMM2: y = h @ w2t^T (fp32 out)
__global__ __launch_bounds__(256, 1)
void k_gemm2_mma() {
    int e   = blockIdx.z;
    int cnt = g_count[e];
    int m0  = blockIdx.y * 128;
    if (m0 >= cnt) return;
    int n0   = blockIdx.x * 128;
    int base = g_offs[e];

    extern __shared__ char smem[];
    uint32_t ub = (smem_u32(smem) + 1023u) & ~1023u;
    int tid = threadIdx.x, lane = tid & 31, wid = tid >> 5;
    int wm0 = (wid >> 2) * 64, wn0 = (wid & 3) * 32;

    const __half* Ah = g_hh  + (size_t)(base + m0) * H;
    const __half* Al = g_hl  + (size_t)(base + m0) * H;
    const __half* Bh = g_w2h + (size_t)e * D * H + (size_t)n0 * H;

    float acc[4][4][4] = {};
    gemm_main(acc, ub, Ah, Al, Bh, H, H / 64, tid, wm0, wn0, lane);

    int cb = (lane & 3) * 2;
    int mr = lane >> 2;
    #pragma unroll
    for (int nf = 0; nf < 4; nf++) {
        #pragma unroll
        for (int mf = 0; mf < 4; mf++) {
            #pragma unroll
            for (int rr = 0; rr < 2; rr++) {
                int m = m0 + wm0 + mf*16 + mr + rr*8;
                if (m >= cnt) continue;
                float2 v;
                v.x = acc[mf][nf][rr*2];
                v.y = acc[mf][nf][rr*2 + 1];
                *reinterpret_cast<float2*>(
                    g_y + (size_t)(base + m) * D + n0 + wn0 + nf*8 + cb) = v;
            }
        }
    }
}

// ---------------- weighted combine (deterministic) ----------------
__global__ void k_combine(const float* __restrict__ b2, float* __restrict__ out, int T) {
    int t = blockIdx.x;
    if (t >= T) return;
    int   e0 = g_topi[2*t],      e1 = g_topi[2*t+1];
    float w0 = g_topw[2*t],      w1 = g_topw[2*t+1];
    int   s0 = g_pair_slot[2*t], s1 = g_pair_slot[2*t+1];
    const float4* y0 = (const float4*)(g_y + (size_t)s0 * D);
    const float4* y1 = (const float4*)(g_y + (size_t)s1 * D);
    const float4* c0 = (const float4*)(b2 + (size_t)e0 * D);
    const float4* c1 = (const float4*)(b2 + (size_t)e1 * D);
    float4* o = (float4*)(out + (size_t)t * D);
    for (int j = threadIdx.x; j < D/4; j += blockDim.x) {
        float4 a = y0[j], b = y1[j], ba = c0[j], bb = c1[j];
        float4 r;
        r.x = w0*(a.x + ba.x) + w1*(b.x + bb.x);
        r.y = w0*(a.y + ba.y) + w1*(b.y + bb.y);
        r.z = w0*(a.z + ba.z) + w1*(b.z + bb.z);
        r.w = w0*(a.w + ba.w) + w1*(b.w + bb.w);
        o[j] = r;
    }
}

// ---------------- launch ----------------
extern "C" void kernel_launch(void* const* d_in, const int* in_sizes, int n_in,
                              void* d_out, int out_size) {
    const float* x  = (const float*)d_in[0];
    const float* rw = (const float*)d_in[1];
    const float* rb = (const float*)d_in[2];
    const float* w1 = (const float*)d_in[3];
    const float* b1 = (const float*)d_in[4];
    const float* w2 = (const float*)d_in[5];
    const float* b2 = (const float*)d_in[6];
    float* out = (float*)d_out;

    int T = in_sizes[0] / D;                 // 4096
    float* auxp = (out_size > T * D) ? (out + (size_t)T * D) : nullptr;

    cudaFuncSetAttribute(k_gemm1_mma, cudaFuncAttributeMaxDynamicSharedMemorySize, SMEM_DYN);
    cudaFuncSetAttribute(k_gemm2_mma, cudaFuncAttributeMaxDynamicSharedMemorySize, SMEM_DYN);

    k_zero<<<1, 32>>>();

    // weight transpose + fp16 convert (independent of router)
    dim3 tb(32, 8);
    k_wsplit<<<dim3(H/32, D/32, E), tb>>>(w1, D, H, 0);
    k_wsplit<<<dim3(D/32, H/32, E), tb>>>(w2, H, D, 1);

    k_router<<<(T + 7) / 8, 256>>>(x, rw, rb, T);
    k_offs_aux<<<1, 1>>>(auxp, T);
    k_scatter<<<(T + 255) / 256, 256>>>(T);
    k_gather<<<2 * T, 256>>>(x);

    int mtiles = (2 * T + 127) / 128;        // upper bound on any expert's tiles
    k_gemm1_mma<<<dim3(H/128, mtiles, E), 256, SMEM_DYN>>>(b1);
    k_gemm2_mma<<<dim3(D/128, mtiles, E), 256, SMEM_DYN>>>();

    k_combine<<<T, 256>>>(b2, out, T);
}